// round 4
// baseline (speedup 1.0000x reference)
#include <cuda_runtime.h>

// ----------------------------------------------------------------------------
// GCN 5-layer inference, N=50000 nodes, E=800000 edges, 128->64->64->64->64->16
//
// Output layout (flattened tuple): [log_softmax N*16][e1 N*64][e2][e3][e4][e5 N*16]
//
// Per layer: XW = relu(e_prev) @ W (dense, fused relu on load)
//            e  = bias-broadcast, then scatter: e[row] += w * XW[col]  (vector RED)
// ----------------------------------------------------------------------------

constexpr int N_NODES = 50000;
constexpr int N_EDGES = 800000;

// Scratch for the per-layer dense GEMM result (max N x 64 fp32 = 12.8 MB).
__device__ float g_xw[(size_t)N_NODES * 64];

// ----------------------------------------------------------------------------
// Dense GEMM: out(g_xw)[N x COLS] = act(X)[N x K] @ W[K x COLS]
// 64-row tile per block; thread tile = 4 rows x 4 cols; K chunked by 64.
// ----------------------------------------------------------------------------
template <int K, int COLS, bool RELU>
__global__ void gemm_kernel(const float* __restrict__ X, const float* __restrict__ W) {
    constexpr int TX = COLS / 4;     // threads along columns
    constexpr int NT = TX * 16;      // block size (16 row-groups)

    __shared__ float sx[64][68];     // [row][k] padded: +4 floats keeps 16B align, kills conflicts
    __shared__ float sw[64][COLS];   // [k][col]

    const int tid  = threadIdx.x;
    const int tx   = tid % TX;
    const int ty   = tid / TX;
    const int row0 = blockIdx.x * 64;

    float4 acc[4];
#pragma unroll
    for (int r = 0; r < 4; r++) acc[r] = make_float4(0.f, 0.f, 0.f, 0.f);

    for (int kt = 0; kt < K; kt += 64) {
        if (kt) __syncthreads();

        // Load X tile: 64 rows x 64 k values (float4-vectorized, relu fused)
        for (int i = tid; i < 64 * 16; i += NT) {
            int r = i >> 4, q = i & 15;
            int gr = row0 + r;
            float4 v = make_float4(0.f, 0.f, 0.f, 0.f);
            if (gr < N_NODES)
                v = *(const float4*)(X + (size_t)gr * K + kt + q * 4);
            if (RELU) {
                v.x = fmaxf(v.x, 0.f); v.y = fmaxf(v.y, 0.f);
                v.z = fmaxf(v.z, 0.f); v.w = fmaxf(v.w, 0.f);
            }
            *(float4*)&sx[r][q * 4] = v;
        }
        // Load W tile: 64 x COLS
        for (int i = tid; i < 64 * (COLS / 4); i += NT) {
            int k = i / (COLS / 4), q = i % (COLS / 4);
            *(float4*)&sw[k][q * 4] = *(const float4*)(W + (size_t)(kt + k) * COLS + q * 4);
        }
        __syncthreads();

#pragma unroll
        for (int k = 0; k < 64; k += 4) {
            float4 b0 = *(const float4*)&sw[k + 0][tx * 4];
            float4 b1 = *(const float4*)&sw[k + 1][tx * 4];
            float4 b2 = *(const float4*)&sw[k + 2][tx * 4];
            float4 b3 = *(const float4*)&sw[k + 3][tx * 4];
#pragma unroll
            for (int r = 0; r < 4; r++) {
                float4 a = *(const float4*)&sx[ty * 4 + r][k];
                acc[r].x += a.x * b0.x; acc[r].y += a.x * b0.y;
                acc[r].z += a.x * b0.z; acc[r].w += a.x * b0.w;
                acc[r].x += a.y * b1.x; acc[r].y += a.y * b1.y;
                acc[r].z += a.y * b1.z; acc[r].w += a.y * b1.w;
                acc[r].x += a.z * b2.x; acc[r].y += a.z * b2.y;
                acc[r].z += a.z * b2.z; acc[r].w += a.z * b2.w;
                acc[r].x += a.w * b3.x; acc[r].y += a.w * b3.y;
                acc[r].z += a.w * b3.z; acc[r].w += a.w * b3.w;
            }
        }
    }

#pragma unroll
    for (int r = 0; r < 4; r++) {
        int gr = row0 + ty * 4 + r;
        if (gr < N_NODES)
            *(float4*)(g_xw + (size_t)gr * COLS + tx * 4) = acc[r];
    }
}

// ----------------------------------------------------------------------------
// Initialize e-buffer rows with the bias vector (segment_sum starts at b).
// ----------------------------------------------------------------------------
template <int C>
__global__ void fill_bias_kernel(float* __restrict__ dst, const float* __restrict__ b, int total4) {
    int t = blockIdx.x * blockDim.x + threadIdx.x;
    if (t >= total4) return;
    int q = t % (C / 4);
    float4 bv = *(const float4*)(b + q * 4);
    ((float4*)dst)[t] = bv;
}

// ----------------------------------------------------------------------------
// Edge scatter: dst[row[e]][:] += w[e] * g_xw[col[e]][:]
// One thread per (edge, 4-feature chunk); vector reduction, no return value.
// ----------------------------------------------------------------------------
__global__ void scatter64_kernel(const int* __restrict__ erow, const int* __restrict__ ecol,
                                 const float* __restrict__ ew, float* __restrict__ dst) {
    int t = blockIdx.x * blockDim.x + threadIdx.x;
    if (t >= N_EDGES * 16) return;
    int e = t >> 4, q = t & 15;
    int r = __ldg(erow + e);
    int c = __ldg(ecol + e);
    float w = __ldg(ew + e);
    float4 v = *(const float4*)(g_xw + (size_t)c * 64 + q * 4);
    float* p = dst + (size_t)r * 64 + q * 4;
    asm volatile("red.global.add.v4.f32 [%0], {%1, %2, %3, %4};"
                 :: "l"(p), "f"(v.x * w), "f"(v.y * w), "f"(v.z * w), "f"(v.w * w)
                 : "memory");
}

__global__ void scatter16_kernel(const int* __restrict__ erow, const int* __restrict__ ecol,
                                 const float* __restrict__ ew, float* __restrict__ dst) {
    int t = blockIdx.x * blockDim.x + threadIdx.x;
    if (t >= N_EDGES * 4) return;
    int e = t >> 2, q = t & 3;
    int r = __ldg(erow + e);
    int c = __ldg(ecol + e);
    float w = __ldg(ew + e);
    float4 v = *(const float4*)(g_xw + (size_t)c * 16 + q * 4);
    float* p = dst + (size_t)r * 16 + q * 4;
    asm volatile("red.global.add.v4.f32 [%0], {%1, %2, %3, %4};"
                 :: "l"(p), "f"(v.x * w), "f"(v.y * w), "f"(v.z * w), "f"(v.w * w)
                 : "memory");
}

// ----------------------------------------------------------------------------
// Row-wise log_softmax over 16 classes (one thread per node row).
// ----------------------------------------------------------------------------
__global__ void logsoftmax_kernel(const float* __restrict__ e5, float* __restrict__ out) {
    int r = blockIdx.x * blockDim.x + threadIdx.x;
    if (r >= N_NODES) return;
    const float4* p = (const float4*)(e5 + (size_t)r * 16);
    float4 v[4];
#pragma unroll
    for (int i = 0; i < 4; i++) v[i] = p[i];

    float m = -1e30f;
#pragma unroll
    for (int i = 0; i < 4; i++) {
        m = fmaxf(m, v[i].x); m = fmaxf(m, v[i].y);
        m = fmaxf(m, v[i].z); m = fmaxf(m, v[i].w);
    }
    float s = 0.f;
#pragma unroll
    for (int i = 0; i < 4; i++) {
        s += expf(v[i].x - m) + expf(v[i].y - m) + expf(v[i].z - m) + expf(v[i].w - m);
    }
    float lse = m + logf(s);
    float4* o = (float4*)(out + (size_t)r * 16);
#pragma unroll
    for (int i = 0; i < 4; i++) {
        float4 w4;
        w4.x = v[i].x - lse; w4.y = v[i].y - lse;
        w4.z = v[i].z - lse; w4.w = v[i].w - lse;
        o[i] = w4;
    }
}

// ----------------------------------------------------------------------------
// Launch
// ----------------------------------------------------------------------------
extern "C" void kernel_launch(void* const* d_in, const int* in_sizes, int n_in,
                              void* d_out, int out_size) {
    const float* x    = (const float*)d_in[0];
    const int*   erow = (const int*)d_in[1];
    const int*   ecol = (const int*)d_in[2];
    const float* ew   = (const float*)d_in[3];
    const float* W1 = (const float*)d_in[4];  const float* b1 = (const float*)d_in[5];
    const float* W2 = (const float*)d_in[6];  const float* b2 = (const float*)d_in[7];
    const float* W3 = (const float*)d_in[8];  const float* b3 = (const float*)d_in[9];
    const float* W4 = (const float*)d_in[10]; const float* b4 = (const float*)d_in[11];
    const float* W5 = (const float*)d_in[12]; const float* b5 = (const float*)d_in[13];

    float* out = (float*)d_out;
    float* e1 = out + (size_t)N_NODES * 16;
    float* e2 = e1 + (size_t)N_NODES * 64;
    float* e3 = e2 + (size_t)N_NODES * 64;
    float* e4 = e3 + (size_t)N_NODES * 64;
    float* e5 = e4 + (size_t)N_NODES * 64;

    const int GB = (N_NODES + 63) / 64;                 // 782 gemm blocks
    const int F64_4 = N_NODES * 16;                     // float4 count for N x 64
    const int F16_4 = N_NODES * 4;                      // float4 count for N x 16
    const int SC64_B = (N_EDGES * 16 + 255) / 256;      // scatter64 blocks
    const int SC16_B = (N_EDGES * 4 + 255) / 256;       // scatter16 blocks

    // Layer 1: 128 -> 64 (no relu on input x)
    gemm_kernel<128, 64, false><<<GB, 256>>>(x, W1);
    fill_bias_kernel<64><<<(F64_4 + 255) / 256, 256>>>(e1, b1, F64_4);
    scatter64_kernel<<<SC64_B, 256>>>(erow, ecol, ew, e1);

    // Layer 2
    gemm_kernel<64, 64, true><<<GB, 256>>>(e1, W2);
    fill_bias_kernel<64><<<(F64_4 + 255) / 256, 256>>>(e2, b2, F64_4);
    scatter64_kernel<<<SC64_B, 256>>>(erow, ecol, ew, e2);

    // Layer 3
    gemm_kernel<64, 64, true><<<GB, 256>>>(e2, W3);
    fill_bias_kernel<64><<<(F64_4 + 255) / 256, 256>>>(e3, b3, F64_4);
    scatter64_kernel<<<SC64_B, 256>>>(erow, ecol, ew, e3);

    // Layer 4
    gemm_kernel<64, 64, true><<<GB, 256>>>(e3, W4);
    fill_bias_kernel<64><<<(F64_4 + 255) / 256, 256>>>(e4, b4, F64_4);
    scatter64_kernel<<<SC64_B, 256>>>(erow, ecol, ew, e4);

    // Layer 5: 64 -> 16
    gemm_kernel<64, 16, true><<<GB, 64>>>(e4, W5);
    fill_bias_kernel<16><<<(F16_4 + 255) / 256, 256>>>(e5, b5, F16_4);
    scatter16_kernel<<<SC16_B, 256>>>(erow, ecol, ew, e5);

    // log_softmax(e5) -> out[0 : N*16]
    logsoftmax_kernel<<<(N_NODES + 127) / 128, 128>>>(e5, out);
}

// round 7
// speedup vs baseline: 1.3428x; 1.3428x over previous
#include <cuda_runtime.h>

// ----------------------------------------------------------------------------
// GCN 5-layer inference, N=50000 nodes, E=800000 edges, 128->64->64->64->64->16
//
// Output layout (flattened tuple): [log_softmax N*16][e1 N*64][e2][e3][e4][e5 N*16]
//
// Strategy:
//   - Build CSR (row-sorted edge list) ONCE per launch: histogram -> scan -> fill.
//   - Per-row register aggregation instead of per-edge RED scatter:
//     each output row written once (16x less write traffic), bias fused as init.
//   - Dense GEMMs: smem-tiled fp32, relu fused on load.
// ----------------------------------------------------------------------------

constexpr int N_NODES = 50000;
constexpr int N_EDGES = 800000;
constexpr int SCAN_CHUNK = 1024;                              // elements per scan block
constexpr int NB = (N_NODES + SCAN_CHUNK - 1) / SCAN_CHUNK;   // 49 scan blocks

// Scratch for the per-layer dense GEMM result (max N x 64 fp32 = 12.8 MB).
__device__ float g_xw[(size_t)N_NODES * 64];

// CSR scratch
__device__ int   g_deg[N_NODES];        // histogram, then reused as fill cursor
__device__ int   g_off[N_NODES + 1];    // exclusive prefix offsets
__device__ int   g_bsum[NB];            // scan block partials
__device__ int   g_ecol[N_EDGES];       // row-sorted cols
__device__ float g_ew[N_EDGES];         // row-sorted weights

// ----------------------------------------------------------------------------
// Dense GEMM: g_xw[N x COLS] = act(X)[N x K] @ W[K x COLS]
// 64-row tile per block; thread tile = 4 rows x 4 cols; K chunked by 64.
// ----------------------------------------------------------------------------
template <int K, int COLS, bool RELU>
__global__ void gemm_kernel(const float* __restrict__ X, const float* __restrict__ W) {
    constexpr int TX = COLS / 4;
    constexpr int NT = TX * 16;

    __shared__ float sx[64][68];     // +4 floats: 16B-aligned skew, conflict-free
    __shared__ float sw[64][COLS];

    const int tid  = threadIdx.x;
    const int tx   = tid % TX;
    const int ty   = tid / TX;
    const int row0 = blockIdx.x * 64;

    float4 acc[4];
#pragma unroll
    for (int r = 0; r < 4; r++) acc[r] = make_float4(0.f, 0.f, 0.f, 0.f);

    for (int kt = 0; kt < K; kt += 64) {
        if (kt) __syncthreads();

        for (int i = tid; i < 64 * 16; i += NT) {
            int r = i >> 4, q = i & 15;
            int gr = row0 + r;
            float4 v = make_float4(0.f, 0.f, 0.f, 0.f);
            if (gr < N_NODES)
                v = *(const float4*)(X + (size_t)gr * K + kt + q * 4);
            if (RELU) {
                v.x = fmaxf(v.x, 0.f); v.y = fmaxf(v.y, 0.f);
                v.z = fmaxf(v.z, 0.f); v.w = fmaxf(v.w, 0.f);
            }
            *(float4*)&sx[r][q * 4] = v;
        }
        for (int i = tid; i < 64 * (COLS / 4); i += NT) {
            int k = i / (COLS / 4), q = i % (COLS / 4);
            *(float4*)&sw[k][q * 4] = *(const float4*)(W + (size_t)(kt + k) * COLS + q * 4);
        }
        __syncthreads();

#pragma unroll
        for (int k = 0; k < 64; k += 4) {
            float4 b0 = *(const float4*)&sw[k + 0][tx * 4];
            float4 b1 = *(const float4*)&sw[k + 1][tx * 4];
            float4 b2 = *(const float4*)&sw[k + 2][tx * 4];
            float4 b3 = *(const float4*)&sw[k + 3][tx * 4];
#pragma unroll
            for (int r = 0; r < 4; r++) {
                float4 a = *(const float4*)&sx[ty * 4 + r][k];
                acc[r].x += a.x * b0.x; acc[r].y += a.x * b0.y;
                acc[r].z += a.x * b0.z; acc[r].w += a.x * b0.w;
                acc[r].x += a.y * b1.x; acc[r].y += a.y * b1.y;
                acc[r].z += a.y * b1.z; acc[r].w += a.y * b1.w;
                acc[r].x += a.z * b2.x; acc[r].y += a.z * b2.y;
                acc[r].z += a.z * b2.z; acc[r].w += a.z * b2.w;
                acc[r].x += a.w * b3.x; acc[r].y += a.w * b3.y;
                acc[r].z += a.w * b3.z; acc[r].w += a.w * b3.w;
            }
        }
    }

#pragma unroll
    for (int r = 0; r < 4; r++) {
        int gr = row0 + ty * 4 + r;
        if (gr < N_NODES)
            *(float4*)(g_xw + (size_t)gr * COLS + tx * 4) = acc[r];
    }
}

// ----------------------------------------------------------------------------
// CSR build
// ----------------------------------------------------------------------------
__global__ void zero_deg_kernel() {
    int i = blockIdx.x * blockDim.x + threadIdx.x;
    if (i < N_NODES) g_deg[i] = 0;
}

__global__ void hist_kernel(const int* __restrict__ erow) {
    int e = blockIdx.x * blockDim.x + threadIdx.x;
    if (e < N_EDGES) atomicAdd(&g_deg[__ldg(erow + e)], 1);
}

// Phase 1: per-block scan of 1024 degrees (256 threads x 4 elems)
__global__ void scan1_kernel() {
    __shared__ int sh[256];
    int b = blockIdx.x, t = threadIdx.x;
    int base = b * SCAN_CHUNK + t * 4;
    int d0 = 0, d1 = 0, d2 = 0, d3 = 0;
    if (base + 0 < N_NODES) d0 = g_deg[base + 0];
    if (base + 1 < N_NODES) d1 = g_deg[base + 1];
    if (base + 2 < N_NODES) d2 = g_deg[base + 2];
    if (base + 3 < N_NODES) d3 = g_deg[base + 3];
    int s = d0 + d1 + d2 + d3;
    sh[t] = s;
    __syncthreads();
    for (int off = 1; off < 256; off <<= 1) {
        int v = (t >= off) ? sh[t - off] : 0;
        __syncthreads();
        sh[t] += v;
        __syncthreads();
    }
    int excl = sh[t] - s;
    if (t == 255) g_bsum[b] = sh[255];
    if (base + 0 < N_NODES) g_off[base + 0] = excl;
    if (base + 1 < N_NODES) g_off[base + 1] = excl + d0;
    if (base + 2 < N_NODES) g_off[base + 2] = excl + d0 + d1;
    if (base + 3 < N_NODES) g_off[base + 3] = excl + d0 + d1 + d2;
}

// Phase 2: single-block exclusive scan of NB block sums (NB = 49 <= 64)
__global__ void scan2_kernel() {
    __shared__ int sh[64];
    int t = threadIdx.x;
    int v = (t < NB) ? g_bsum[t] : 0;
    sh[t] = v;
    __syncthreads();
    for (int off = 1; off < 64; off <<= 1) {
        int u = (t >= off) ? sh[t - off] : 0;
        __syncthreads();
        sh[t] += u;
        __syncthreads();
    }
    if (t < NB) g_bsum[t] = sh[t] - v;   // exclusive
}

// Phase 3: add block bases, zero cursor (reuse g_deg), set sentinel
__global__ void scan3_kernel() {
    int i = blockIdx.x * blockDim.x + threadIdx.x;
    if (i < N_NODES) {
        g_off[i] += g_bsum[i / SCAN_CHUNK];
        g_deg[i] = 0;                    // fill cursor
    }
    if (i == 0) g_off[N_NODES] = N_EDGES;
}

__global__ void fill_kernel(const int* __restrict__ erow, const int* __restrict__ ecol,
                            const float* __restrict__ ew) {
    int e = blockIdx.x * blockDim.x + threadIdx.x;
    if (e >= N_EDGES) return;
    int r = __ldg(erow + e);
    int pos = g_off[r] + atomicAdd(&g_deg[r], 1);
    g_ecol[pos] = __ldg(ecol + e);
    g_ew[pos]   = __ldg(ew + e);
}

// ----------------------------------------------------------------------------
// Per-row aggregation: dst[row][:] = b + sum_{e in row} w_e * g_xw[col_e][:]
// Thread owns (row, 4-feature chunk). 16 threads (half warp) share a row, so
// the g_ecol/g_ew loads are warp-broadcast (one sector per read). Accumulate
// in registers, write the row slice exactly once.
// ----------------------------------------------------------------------------
__global__ void agg64_kernel(const float* __restrict__ bias, float* __restrict__ dst) {
    int t = blockIdx.x * blockDim.x + threadIdx.x;
    if (t >= N_NODES * 16) return;
    int row = t >> 4, q = t & 15;
    float4 acc = *(const float4*)(bias + q * 4);
    int i = __ldg(&g_off[row]), end = __ldg(&g_off[row + 1]);
    for (; i + 1 < end; i += 2) {
        int c0 = __ldg(&g_ecol[i]);     float w0 = __ldg(&g_ew[i]);
        int c1 = __ldg(&g_ecol[i + 1]); float w1 = __ldg(&g_ew[i + 1]);
        float4 v0 = *(const float4*)(g_xw + (size_t)c0 * 64 + q * 4);
        float4 v1 = *(const float4*)(g_xw + (size_t)c1 * 64 + q * 4);
        acc.x += w0 * v0.x + w1 * v1.x;
        acc.y += w0 * v0.y + w1 * v1.y;
        acc.z += w0 * v0.z + w1 * v1.z;
        acc.w += w0 * v0.w + w1 * v1.w;
    }
    if (i < end) {
        int c = __ldg(&g_ecol[i]); float w = __ldg(&g_ew[i]);
        float4 v = *(const float4*)(g_xw + (size_t)c * 64 + q * 4);
        acc.x += w * v.x; acc.y += w * v.y; acc.z += w * v.z; acc.w += w * v.w;
    }
    *(float4*)(dst + (size_t)row * 64 + q * 4) = acc;
}

__global__ void agg16_kernel(const float* __restrict__ bias, float* __restrict__ dst) {
    int t = blockIdx.x * blockDim.x + threadIdx.x;
    if (t >= N_NODES * 4) return;
    int row = t >> 2, q = t & 3;
    float4 acc = *(const float4*)(bias + q * 4);
    int i = __ldg(&g_off[row]), end = __ldg(&g_off[row + 1]);
    for (; i + 1 < end; i += 2) {
        int c0 = __ldg(&g_ecol[i]);     float w0 = __ldg(&g_ew[i]);
        int c1 = __ldg(&g_ecol[i + 1]); float w1 = __ldg(&g_ew[i + 1]);
        float4 v0 = *(const float4*)(g_xw + (size_t)c0 * 16 + q * 4);
        float4 v1 = *(const float4*)(g_xw + (size_t)c1 * 16 + q * 4);
        acc.x += w0 * v0.x + w1 * v1.x;
        acc.y += w0 * v0.y + w1 * v1.y;
        acc.z += w0 * v0.z + w1 * v1.z;
        acc.w += w0 * v0.w + w1 * v1.w;
    }
    if (i < end) {
        int c = __ldg(&g_ecol[i]); float w = __ldg(&g_ew[i]);
        float4 v = *(const float4*)(g_xw + (size_t)c * 16 + q * 4);
        acc.x += w * v.x; acc.y += w * v.y; acc.z += w * v.z; acc.w += w * v.w;
    }
    *(float4*)(dst + (size_t)row * 16 + q * 4) = acc;
}

// ----------------------------------------------------------------------------
// Row-wise log_softmax over 16 classes (one thread per node row).
// ----------------------------------------------------------------------------
__global__ void logsoftmax_kernel(const float* __restrict__ e5, float* __restrict__ out) {
    int r = blockIdx.x * blockDim.x + threadIdx.x;
    if (r >= N_NODES) return;
    const float4* p = (const float4*)(e5 + (size_t)r * 16);
    float4 v[4];
#pragma unroll
    for (int i = 0; i < 4; i++) v[i] = p[i];

    float m = -1e30f;
#pragma unroll
    for (int i = 0; i < 4; i++) {
        m = fmaxf(m, v[i].x); m = fmaxf(m, v[i].y);
        m = fmaxf(m, v[i].z); m = fmaxf(m, v[i].w);
    }
    float s = 0.f;
#pragma unroll
    for (int i = 0; i < 4; i++) {
        s += expf(v[i].x - m) + expf(v[i].y - m) + expf(v[i].z - m) + expf(v[i].w - m);
    }
    float lse = m + logf(s);
    float4* o = (float4*)(out + (size_t)r * 16);
#pragma unroll
    for (int i = 0; i < 4; i++) {
        float4 w4;
        w4.x = v[i].x - lse; w4.y = v[i].y - lse;
        w4.z = v[i].z - lse; w4.w = v[i].w - lse;
        o[i] = w4;
    }
}

// ----------------------------------------------------------------------------
// Launch
// ----------------------------------------------------------------------------
extern "C" void kernel_launch(void* const* d_in, const int* in_sizes, int n_in,
                              void* d_out, int out_size) {
    const float* x    = (const float*)d_in[0];
    const int*   erow = (const int*)d_in[1];
    const int*   ecol = (const int*)d_in[2];
    const float* ew   = (const float*)d_in[3];
    const float* W1 = (const float*)d_in[4];  const float* b1 = (const float*)d_in[5];
    const float* W2 = (const float*)d_in[6];  const float* b2 = (const float*)d_in[7];
    const float* W3 = (const float*)d_in[8];  const float* b3 = (const float*)d_in[9];
    const float* W4 = (const float*)d_in[10]; const float* b4 = (const float*)d_in[11];
    const float* W5 = (const float*)d_in[12]; const float* b5 = (const float*)d_in[13];

    float* out = (float*)d_out;
    float* e1 = out + (size_t)N_NODES * 16;
    float* e2 = e1 + (size_t)N_NODES * 64;
    float* e3 = e2 + (size_t)N_NODES * 64;
    float* e4 = e3 + (size_t)N_NODES * 64;
    float* e5 = e4 + (size_t)N_NODES * 64;

    const int GB    = (N_NODES + 63) / 64;
    const int NB_N  = (N_NODES + 255) / 256;
    const int NB_E  = (N_EDGES + 255) / 256;
    const int AGG64 = (N_NODES * 16 + 255) / 256;
    const int AGG16 = (N_NODES * 4 + 255) / 256;

    // Layer-1 GEMM first, then CSR build (independent work back-to-back).
    gemm_kernel<128, 64, false><<<GB, 256>>>(x, W1);
    zero_deg_kernel<<<NB_N, 256>>>();
    hist_kernel<<<NB_E, 256>>>(erow);
    scan1_kernel<<<NB, 256>>>();
    scan2_kernel<<<1, 64>>>();
    scan3_kernel<<<NB_N, 256>>>();
    fill_kernel<<<NB_E, 256>>>(erow, ecol, ew);

    // Layer 1 aggregation
    agg64_kernel<<<AGG64, 256>>>(b1, e1);

    // Layer 2
    gemm_kernel<64, 64, true><<<GB, 256>>>(e1, W2);
    agg64_kernel<<<AGG64, 256>>>(b2, e2);

    // Layer 3
    gemm_kernel<64, 64, true><<<GB, 256>>>(e2, W3);
    agg64_kernel<<<AGG64, 256>>>(b3, e3);

    // Layer 4
    gemm_kernel<64, 64, true><<<GB, 256>>>(e3, W4);
    agg64_kernel<<<AGG64, 256>>>(b4, e4);

    // Layer 5: 64 -> 16
    gemm_kernel<64, 16, true><<<GB, 64>>>(e4, W5);
    agg16_kernel<<<AGG16, 256>>>(b5, e5);

    // log_softmax(e5) -> out[0 : N*16]
    logsoftmax_kernel<<<(N_NODES + 127) / 128, 128>>>(e5, out);
}